// round 2
// baseline (speedup 1.0000x reference)
#include <cuda_runtime.h>
#include <cuda_bf16.h>

#define N_NODES 100000
#define N_EDGES 1600000
#define DIM 64
#define N_GRAPHS 128
#define N_LAYERS 5
#define BN_EPS 1e-5f

// Scratch (allocation-free rule: __device__ globals)
__device__ float g_h[N_NODES * DIM];     // layer output
__device__ float g_agg[N_NODES * DIM];   // h + sum_{neighbors}
__device__ float g_pool[N_GRAPHS * DIM]; // pooled per-graph sums

// ---------------------------------------------------------------------------
// agg[i] = h[i]  (self term of GIN; scatter adds neighbors on top)
// ---------------------------------------------------------------------------
__global__ void init_agg_kernel(const float* __restrict__ h, float* __restrict__ agg) {
    int i = blockIdx.x * blockDim.x + threadIdx.x; // float4 index
    if (i < N_NODES * DIM / 4) {
        reinterpret_cast<float4*>(agg)[i] = reinterpret_cast<const float4*>(h)[i];
    }
}

// ---------------------------------------------------------------------------
// Edge scatter: agg[dst] += h[src].  16 threads per edge, float4 gather.
// Indices are int32 (JAX default x64-disabled downcasts int64 -> int32).
// ---------------------------------------------------------------------------
__global__ void scatter_kernel(const float* __restrict__ h,
                               const int* __restrict__ ei,
                               float* __restrict__ agg) {
    long long idx = (long long)blockIdx.x * blockDim.x + threadIdx.x;
    int e = (int)(idx >> 4);
    int c = (int)((idx & 15) << 2); // starting dim (0,4,...,60)
    if (e >= N_EDGES) return;
    int s = ei[e];
    int d = ei[N_EDGES + e];
    float4 v = *reinterpret_cast<const float4*>(&h[(long long)s * DIM + c]);
    float* p = &agg[(long long)d * DIM + c];
    atomicAdd(p + 0, v.x);
    atomicAdd(p + 1, v.y);
    atomicAdd(p + 2, v.z);
    atomicAdd(p + 3, v.w);
}

// ---------------------------------------------------------------------------
// Fused node MLP: out = relu( relu(BN(x@W1 + b1)) @ W2 + b2 )
// Block: 256 threads, 64 nodes. Each thread: 4 nodes x 4 dims.
// ---------------------------------------------------------------------------
__global__ void __launch_bounds__(256) mlp_kernel(
    const float* __restrict__ x, float* __restrict__ out,
    const float* __restrict__ W1, const float* __restrict__ b1,
    const float* __restrict__ gamma, const float* __restrict__ beta,
    const float* __restrict__ rmean, const float* __restrict__ rvar,
    const float* __restrict__ W2, const float* __restrict__ b2) {
    __shared__ float sW[DIM][DIM];       // 16 KB, W1 then W2
    __shared__ float sX[DIM][DIM + 1];   // 16.25 KB, x tile then t tile
    __shared__ float sA[DIM], sB[DIM];   // BN fold: t = relu(dot*A + B)

    int tid = threadIdx.x;
    int node0 = blockIdx.x * 64;

    // load W1
    for (int i = tid; i < DIM * DIM; i += 256) sW[i >> 6][i & 63] = W1[i];
    if (tid < DIM) {
        float s = gamma[tid] * rsqrtf(rvar[tid] + BN_EPS);
        sA[tid] = s;
        sB[tid] = (b1[tid] - rmean[tid]) * s + beta[tid];
    }
    // load x tile (zero-pad OOB nodes)
    for (int i = tid; i < DIM * DIM; i += 256) {
        int r = i >> 6, c = i & 63;
        int node = node0 + r;
        sX[r][c] = (node < N_NODES) ? x[(long long)node * DIM + c] : 0.f;
    }
    __syncthreads();

    int nd = tid & 15;  // dim group: dims [nd*4, nd*4+4)
    int ng = tid >> 4;  // node base: nodes {ng, ng+16, ng+32, ng+48}

    // ---- GEMM 1 ----
    float acc[4][4];
#pragma unroll
    for (int i = 0; i < 4; i++)
#pragma unroll
        for (int j = 0; j < 4; j++) acc[i][j] = 0.f;

#pragma unroll 8
    for (int k = 0; k < DIM; k++) {
        float4 w = *reinterpret_cast<const float4*>(&sW[k][nd * 4]);
        float x0 = sX[ng][k];
        float x1 = sX[ng + 16][k];
        float x2 = sX[ng + 32][k];
        float x3 = sX[ng + 48][k];
        acc[0][0] += x0 * w.x; acc[0][1] += x0 * w.y; acc[0][2] += x0 * w.z; acc[0][3] += x0 * w.w;
        acc[1][0] += x1 * w.x; acc[1][1] += x1 * w.y; acc[1][2] += x1 * w.z; acc[1][3] += x1 * w.w;
        acc[2][0] += x2 * w.x; acc[2][1] += x2 * w.y; acc[2][2] += x2 * w.z; acc[2][3] += x2 * w.w;
        acc[3][0] += x3 * w.x; acc[3][1] += x3 * w.y; acc[3][2] += x3 * w.z; acc[3][3] += x3 * w.w;
    }
    __syncthreads(); // all reads of sW/sX done

    // BN + relu, stash t into sX; load W2
#pragma unroll
    for (int i = 0; i < 4; i++) {
#pragma unroll
        for (int j = 0; j < 4; j++) {
            int d = nd * 4 + j;
            sX[ng + 16 * i][d] = fmaxf(acc[i][j] * sA[d] + sB[d], 0.f);
        }
    }
    for (int i = tid; i < DIM * DIM; i += 256) sW[i >> 6][i & 63] = W2[i];
    __syncthreads();

    // ---- GEMM 2 ----
#pragma unroll
    for (int i = 0; i < 4; i++)
#pragma unroll
        for (int j = 0; j < 4; j++) acc[i][j] = 0.f;

#pragma unroll 8
    for (int k = 0; k < DIM; k++) {
        float4 w = *reinterpret_cast<const float4*>(&sW[k][nd * 4]);
        float x0 = sX[ng][k];
        float x1 = sX[ng + 16][k];
        float x2 = sX[ng + 32][k];
        float x3 = sX[ng + 48][k];
        acc[0][0] += x0 * w.x; acc[0][1] += x0 * w.y; acc[0][2] += x0 * w.z; acc[0][3] += x0 * w.w;
        acc[1][0] += x1 * w.x; acc[1][1] += x1 * w.y; acc[1][2] += x1 * w.z; acc[1][3] += x1 * w.w;
        acc[2][0] += x2 * w.x; acc[2][1] += x2 * w.y; acc[2][2] += x2 * w.z; acc[2][3] += x2 * w.w;
        acc[3][0] += x3 * w.x; acc[3][1] += x3 * w.y; acc[3][2] += x3 * w.z; acc[3][3] += x3 * w.w;
    }

    // + b2, relu, store
    float4 bb = *reinterpret_cast<const float4*>(&b2[nd * 4]);
#pragma unroll
    for (int i = 0; i < 4; i++) {
        int node = node0 + ng + 16 * i;
        if (node < N_NODES) {
            float4 o;
            o.x = fmaxf(acc[i][0] + bb.x, 0.f);
            o.y = fmaxf(acc[i][1] + bb.y, 0.f);
            o.z = fmaxf(acc[i][2] + bb.z, 0.f);
            o.w = fmaxf(acc[i][3] + bb.w, 0.f);
            *reinterpret_cast<float4*>(&out[(long long)node * DIM + nd * 4]) = o;
        }
    }
}

// ---------------------------------------------------------------------------
// Pool zero + segment-sum pool (batch is sorted -> run-length local accum)
// ---------------------------------------------------------------------------
__global__ void zero_pool_kernel(float* __restrict__ pool) {
    int i = blockIdx.x * blockDim.x + threadIdx.x;
    if (i < N_GRAPHS * DIM) pool[i] = 0.f;
}

__global__ void pool_kernel(const float* __restrict__ h,
                            const int* __restrict__ batch,
                            float* __restrict__ pool) {
    const int NPB = 1024;
    int d = threadIdx.x; // 64 threads = dims
    int start = blockIdx.x * NPB;
    if (start >= N_NODES) return;
    int end = min(start + NPB, N_NODES);
    int g = batch[start];
    float acc = 0.f;
    for (int node = start; node < end; node++) {
        int bg = batch[node];
        if (bg != g) {
            atomicAdd(&pool[g * DIM + d], acc);
            acc = 0.f;
            g = bg;
        }
        acc += h[(long long)node * DIM + d];
    }
    atomicAdd(&pool[g * DIM + d], acc);
}

// ---------------------------------------------------------------------------
// Head: out = relu(pool@lin1_w + lin1_b) @ lin2_w + lin2_b    [128 x 10]
// ---------------------------------------------------------------------------
__global__ void head_kernel(const float* __restrict__ pool,
                            const float* __restrict__ w1, const float* __restrict__ b1v,
                            const float* __restrict__ w2, const float* __restrict__ b2v,
                            float* __restrict__ out) {
    __shared__ float sW[DIM][DIM];      // 16 KB
    __shared__ float sH[N_GRAPHS][DIM]; // 32 KB
    int tid = threadIdx.x; // 128
    for (int i = tid; i < DIM * DIM; i += 128) sW[i >> 6][i & 63] = w1[i];
    __syncthreads();

    int g = tid;
    float row[DIM];
#pragma unroll
    for (int k = 0; k < DIM; k++) row[k] = pool[g * DIM + k];
#pragma unroll 4
    for (int j = 0; j < DIM; j++) {
        float acc = b1v[j];
#pragma unroll
        for (int k = 0; k < DIM; k++) acc += row[k] * sW[k][j];
        sH[g][j] = fmaxf(acc, 0.f);
    }
    __syncthreads();
#pragma unroll
    for (int o = 0; o < 10; o++) {
        float acc = b2v[o];
#pragma unroll
        for (int k = 0; k < DIM; k++) acc += sH[g][k] * w2[k * 10 + o];
        out[g * 10 + o] = acc;
    }
}

// ---------------------------------------------------------------------------
extern "C" void kernel_launch(void* const* d_in, const int* in_sizes, int n_in,
                              void* d_out, int out_size) {
    const float* x      = (const float*)d_in[0];
    const int*   ei     = (const int*)d_in[1];
    const int*   batch  = (const int*)d_in[2];
    const float* W1     = (const float*)d_in[3];
    const float* b1     = (const float*)d_in[4];
    const float* gamma  = (const float*)d_in[5];
    const float* beta   = (const float*)d_in[6];
    const float* rmean  = (const float*)d_in[7];
    const float* rvar   = (const float*)d_in[8];
    const float* W2     = (const float*)d_in[9];
    const float* b2     = (const float*)d_in[10];
    const float* lin1_w = (const float*)d_in[11];
    const float* lin1_b = (const float*)d_in[12];
    const float* lin2_w = (const float*)d_in[13];
    const float* lin2_b = (const float*)d_in[14];
    float* out = (float*)d_out;

    float *h_buf, *agg_buf, *pool_buf;
    cudaGetSymbolAddress((void**)&h_buf, g_h);
    cudaGetSymbolAddress((void**)&agg_buf, g_agg);
    cudaGetSymbolAddress((void**)&pool_buf, g_pool);

    const int copy_threads = 256;
    const int copy_blocks = (N_NODES * DIM / 4 + copy_threads - 1) / copy_threads;
    const long long scat_total = (long long)N_EDGES * 16;
    const int scat_blocks = (int)((scat_total + 255) / 256);
    const int mlp_blocks = (N_NODES + 63) / 64;

    const float* cur = x;
    for (int l = 0; l < N_LAYERS; l++) {
        init_agg_kernel<<<copy_blocks, copy_threads>>>(cur, agg_buf);
        scatter_kernel<<<scat_blocks, 256>>>(cur, ei, agg_buf);
        mlp_kernel<<<mlp_blocks, 256>>>(
            agg_buf, h_buf,
            W1 + l * DIM * DIM, b1 + l * DIM,
            gamma + l * DIM, beta + l * DIM,
            rmean + l * DIM, rvar + l * DIM,
            W2 + l * DIM * DIM, b2 + l * DIM);
        cur = h_buf;
    }

    zero_pool_kernel<<<(N_GRAPHS * DIM + 255) / 256, 256>>>(pool_buf);
    pool_kernel<<<(N_NODES + 1023) / 1024, 64>>>(h_buf, batch, pool_buf);
    head_kernel<<<1, 128>>>(pool_buf, lin1_w, lin1_b, lin2_w, lin2_b, out);
}

// round 3
// speedup vs baseline: 1.9947x; 1.9947x over previous
#include <cuda_runtime.h>
#include <cuda_bf16.h>

#define N_NODES 100000
#define N_EDGES 1600000
#define DIM 64
#define N_GRAPHS 128
#define N_LAYERS 5
#define BN_EPS 1e-5f

#define SCAN_B 1024
#define N_SCAN_BLK ((N_NODES + SCAN_B - 1) / SCAN_B)   // 98

// Scratch (allocation-free rule: __device__ globals)
__device__ float g_h[N_NODES * DIM];
__device__ float g_agg[N_NODES * DIM];
__device__ float g_pool[N_GRAPHS * DIM];
__device__ int   g_deg[N_NODES];
__device__ int   g_rowptr[N_NODES + 1];
__device__ int   g_cursor[N_NODES];
__device__ int   g_esrc[N_EDGES];
__device__ int   g_partials[128];   // >= N_SCAN_BLK

// ---------------------------------------------------------------------------
// CSR build (once per launch; edge_index is layer-invariant)
// ---------------------------------------------------------------------------
__global__ void zero_deg_kernel(int* __restrict__ deg) {
    int i = blockIdx.x * blockDim.x + threadIdx.x;
    if (i < N_NODES) deg[i] = 0;
}

__global__ void hist_kernel(const int* __restrict__ ei, int* __restrict__ deg) {
    int e = blockIdx.x * blockDim.x + threadIdx.x;
    if (e < N_EDGES) atomicAdd(&deg[ei[N_EDGES + e]], 1);
}

// Block-local exclusive scan; writes block totals to partials.
__global__ void scan1_kernel(const int* __restrict__ deg, int* __restrict__ excl,
                             int* __restrict__ partials) {
    __shared__ int sh[SCAN_B];
    int t = threadIdx.x;
    int idx = blockIdx.x * SCAN_B + t;
    int v = (idx < N_NODES) ? deg[idx] : 0;
    sh[t] = v;
    __syncthreads();
#pragma unroll
    for (int off = 1; off < SCAN_B; off <<= 1) {
        int add = (t >= off) ? sh[t - off] : 0;
        __syncthreads();
        sh[t] += add;
        __syncthreads();
    }
    if (idx < N_NODES) excl[idx] = sh[t] - v;        // block-local exclusive
    if (t == SCAN_B - 1) partials[blockIdx.x] = sh[t];
}

// Single-block exclusive scan over partials.
__global__ void scan2_kernel(int* __restrict__ partials) {
    __shared__ int sh[128];
    int t = threadIdx.x;
    int v = (t < N_SCAN_BLK) ? partials[t] : 0;
    sh[t] = v;
    __syncthreads();
#pragma unroll
    for (int off = 1; off < 128; off <<= 1) {
        int add = (t >= off) ? sh[t - off] : 0;
        __syncthreads();
        sh[t] += add;
        __syncthreads();
    }
    if (t < N_SCAN_BLK) partials[t] = sh[t] - v;     // exclusive
}

__global__ void scan3_kernel(int* __restrict__ rowptr, int* __restrict__ cursor,
                             const int* __restrict__ partials) {
    int idx = blockIdx.x * blockDim.x + threadIdx.x;
    if (idx < N_NODES) {
        int val = rowptr[idx] + partials[idx >> 10];
        rowptr[idx] = val;
        cursor[idx] = val;
        if (idx == 0) rowptr[N_NODES] = N_EDGES;
    }
}

__global__ void fill_kernel(const int* __restrict__ ei, int* __restrict__ cursor,
                            int* __restrict__ esrc) {
    int e = blockIdx.x * blockDim.x + threadIdx.x;
    if (e < N_EDGES) {
        int d = ei[N_EDGES + e];
        int pos = atomicAdd(&cursor[d], 1);
        esrc[pos] = ei[e];
    }
}

// ---------------------------------------------------------------------------
// Gather aggregation: agg[i] = h[i] + sum_{j in N(i)} h[j]
// 64 threads per node (one per dim), 4 nodes per block. Coalesced 256B/edge.
// ---------------------------------------------------------------------------
__global__ void __launch_bounds__(256) aggregate_kernel(
    const float* __restrict__ h, float* __restrict__ agg,
    const int* __restrict__ rowptr, const int* __restrict__ esrc) {
    int node = blockIdx.x * 4 + (threadIdx.x >> 6);
    int d = threadIdx.x & 63;
    if (node >= N_NODES) return;
    int beg = rowptr[node];
    int end = rowptr[node + 1];
    float acc = h[node * DIM + d];
    int j = beg;
    for (; j + 3 < end; j += 4) {
        int s0 = esrc[j], s1 = esrc[j + 1], s2 = esrc[j + 2], s3 = esrc[j + 3];
        float v0 = h[s0 * DIM + d];
        float v1 = h[s1 * DIM + d];
        float v2 = h[s2 * DIM + d];
        float v3 = h[s3 * DIM + d];
        acc += v0 + v1 + v2 + v3;
    }
    for (; j < end; j++) acc += h[esrc[j] * DIM + d];
    agg[node * DIM + d] = acc;
}

// ---------------------------------------------------------------------------
// Fused node MLP: out = relu( relu(BN(x@W1 + b1)) @ W2 + b2 )
// ---------------------------------------------------------------------------
__global__ void __launch_bounds__(256) mlp_kernel(
    const float* __restrict__ x, float* __restrict__ out,
    const float* __restrict__ W1, const float* __restrict__ b1,
    const float* __restrict__ gamma, const float* __restrict__ beta,
    const float* __restrict__ rmean, const float* __restrict__ rvar,
    const float* __restrict__ W2, const float* __restrict__ b2) {
    __shared__ float sW[DIM][DIM];
    __shared__ float sX[DIM][DIM + 1];
    __shared__ float sA[DIM], sB[DIM];

    int tid = threadIdx.x;
    int node0 = blockIdx.x * 64;

    for (int i = tid; i < DIM * DIM; i += 256) sW[i >> 6][i & 63] = W1[i];
    if (tid < DIM) {
        float s = gamma[tid] * rsqrtf(rvar[tid] + BN_EPS);
        sA[tid] = s;
        sB[tid] = (b1[tid] - rmean[tid]) * s + beta[tid];
    }
    for (int i = tid; i < DIM * DIM; i += 256) {
        int r = i >> 6, c = i & 63;
        int node = node0 + r;
        sX[r][c] = (node < N_NODES) ? x[node * DIM + c] : 0.f;
    }
    __syncthreads();

    int nd = tid & 15;
    int ng = tid >> 4;

    float acc[4][4];
#pragma unroll
    for (int i = 0; i < 4; i++)
#pragma unroll
        for (int j = 0; j < 4; j++) acc[i][j] = 0.f;

#pragma unroll 8
    for (int k = 0; k < DIM; k++) {
        float4 w = *reinterpret_cast<const float4*>(&sW[k][nd * 4]);
        float x0 = sX[ng][k];
        float x1 = sX[ng + 16][k];
        float x2 = sX[ng + 32][k];
        float x3 = sX[ng + 48][k];
        acc[0][0] += x0 * w.x; acc[0][1] += x0 * w.y; acc[0][2] += x0 * w.z; acc[0][3] += x0 * w.w;
        acc[1][0] += x1 * w.x; acc[1][1] += x1 * w.y; acc[1][2] += x1 * w.z; acc[1][3] += x1 * w.w;
        acc[2][0] += x2 * w.x; acc[2][1] += x2 * w.y; acc[2][2] += x2 * w.z; acc[2][3] += x2 * w.w;
        acc[3][0] += x3 * w.x; acc[3][1] += x3 * w.y; acc[3][2] += x3 * w.z; acc[3][3] += x3 * w.w;
    }
    __syncthreads();

#pragma unroll
    for (int i = 0; i < 4; i++) {
#pragma unroll
        for (int j = 0; j < 4; j++) {
            int d = nd * 4 + j;
            sX[ng + 16 * i][d] = fmaxf(acc[i][j] * sA[d] + sB[d], 0.f);
        }
    }
    for (int i = tid; i < DIM * DIM; i += 256) sW[i >> 6][i & 63] = W2[i];
    __syncthreads();

#pragma unroll
    for (int i = 0; i < 4; i++)
#pragma unroll
        for (int j = 0; j < 4; j++) acc[i][j] = 0.f;

#pragma unroll 8
    for (int k = 0; k < DIM; k++) {
        float4 w = *reinterpret_cast<const float4*>(&sW[k][nd * 4]);
        float x0 = sX[ng][k];
        float x1 = sX[ng + 16][k];
        float x2 = sX[ng + 32][k];
        float x3 = sX[ng + 48][k];
        acc[0][0] += x0 * w.x; acc[0][1] += x0 * w.y; acc[0][2] += x0 * w.z; acc[0][3] += x0 * w.w;
        acc[1][0] += x1 * w.x; acc[1][1] += x1 * w.y; acc[1][2] += x1 * w.z; acc[1][3] += x1 * w.w;
        acc[2][0] += x2 * w.x; acc[2][1] += x2 * w.y; acc[2][2] += x2 * w.z; acc[2][3] += x2 * w.w;
        acc[3][0] += x3 * w.x; acc[3][1] += x3 * w.y; acc[3][2] += x3 * w.z; acc[3][3] += x3 * w.w;
    }

    float4 bb = *reinterpret_cast<const float4*>(&b2[nd * 4]);
#pragma unroll
    for (int i = 0; i < 4; i++) {
        int node = node0 + ng + 16 * i;
        if (node < N_NODES) {
            float4 o;
            o.x = fmaxf(acc[i][0] + bb.x, 0.f);
            o.y = fmaxf(acc[i][1] + bb.y, 0.f);
            o.z = fmaxf(acc[i][2] + bb.z, 0.f);
            o.w = fmaxf(acc[i][3] + bb.w, 0.f);
            *reinterpret_cast<float4*>(&out[node * DIM + nd * 4]) = o;
        }
    }
}

// ---------------------------------------------------------------------------
// Pool + head
// ---------------------------------------------------------------------------
__global__ void zero_pool_kernel(float* __restrict__ pool) {
    int i = blockIdx.x * blockDim.x + threadIdx.x;
    if (i < N_GRAPHS * DIM) pool[i] = 0.f;
}

__global__ void pool_kernel(const float* __restrict__ h,
                            const int* __restrict__ batch,
                            float* __restrict__ pool) {
    const int NPB = 1024;
    int d = threadIdx.x;
    int start = blockIdx.x * NPB;
    if (start >= N_NODES) return;
    int end = min(start + NPB, N_NODES);
    int g = batch[start];
    float acc = 0.f;
    for (int node = start; node < end; node++) {
        int bg = batch[node];
        if (bg != g) {
            atomicAdd(&pool[g * DIM + d], acc);
            acc = 0.f;
            g = bg;
        }
        acc += h[node * DIM + d];
    }
    atomicAdd(&pool[g * DIM + d], acc);
}

__global__ void head_kernel(const float* __restrict__ pool,
                            const float* __restrict__ w1, const float* __restrict__ b1v,
                            const float* __restrict__ w2, const float* __restrict__ b2v,
                            float* __restrict__ out) {
    __shared__ float sW[DIM][DIM];
    __shared__ float sH[N_GRAPHS][DIM];
    int tid = threadIdx.x;
    for (int i = tid; i < DIM * DIM; i += 128) sW[i >> 6][i & 63] = w1[i];
    __syncthreads();

    int g = tid;
    float row[DIM];
#pragma unroll
    for (int k = 0; k < DIM; k++) row[k] = pool[g * DIM + k];
#pragma unroll 4
    for (int j = 0; j < DIM; j++) {
        float acc = b1v[j];
#pragma unroll
        for (int k = 0; k < DIM; k++) acc += row[k] * sW[k][j];
        sH[g][j] = fmaxf(acc, 0.f);
    }
    __syncthreads();
#pragma unroll
    for (int o = 0; o < 10; o++) {
        float acc = b2v[o];
#pragma unroll
        for (int k = 0; k < DIM; k++) acc += sH[g][k] * w2[k * 10 + o];
        out[g * 10 + o] = acc;
    }
}

// ---------------------------------------------------------------------------
extern "C" void kernel_launch(void* const* d_in, const int* in_sizes, int n_in,
                              void* d_out, int out_size) {
    const float* x      = (const float*)d_in[0];
    const int*   ei     = (const int*)d_in[1];
    const int*   batch  = (const int*)d_in[2];
    const float* W1     = (const float*)d_in[3];
    const float* b1     = (const float*)d_in[4];
    const float* gamma  = (const float*)d_in[5];
    const float* beta   = (const float*)d_in[6];
    const float* rmean  = (const float*)d_in[7];
    const float* rvar   = (const float*)d_in[8];
    const float* W2     = (const float*)d_in[9];
    const float* b2     = (const float*)d_in[10];
    const float* lin1_w = (const float*)d_in[11];
    const float* lin1_b = (const float*)d_in[12];
    const float* lin2_w = (const float*)d_in[13];
    const float* lin2_b = (const float*)d_in[14];
    float* out = (float*)d_out;

    float *h_buf, *agg_buf, *pool_buf;
    int *deg, *rowptr, *cursor, *esrc, *partials;
    cudaGetSymbolAddress((void**)&h_buf, g_h);
    cudaGetSymbolAddress((void**)&agg_buf, g_agg);
    cudaGetSymbolAddress((void**)&pool_buf, g_pool);
    cudaGetSymbolAddress((void**)&deg, g_deg);
    cudaGetSymbolAddress((void**)&rowptr, g_rowptr);
    cudaGetSymbolAddress((void**)&cursor, g_cursor);
    cudaGetSymbolAddress((void**)&esrc, g_esrc);
    cudaGetSymbolAddress((void**)&partials, g_partials);

    const int eb = (N_EDGES + 255) / 256;
    const int nb = (N_NODES + 255) / 256;

    // --- CSR build (once; reused by all 5 layers) ---
    zero_deg_kernel<<<nb, 256>>>(deg);
    hist_kernel<<<eb, 256>>>(ei, deg);
    scan1_kernel<<<N_SCAN_BLK, SCAN_B>>>(deg, rowptr, partials);
    scan2_kernel<<<1, 128>>>(partials);
    scan3_kernel<<<nb, 256>>>(rowptr, cursor, partials);
    fill_kernel<<<eb, 256>>>(ei, cursor, esrc);

    // --- 5 GIN layers ---
    const int agg_blocks = (N_NODES + 3) / 4;
    const int mlp_blocks = (N_NODES + 63) / 64;
    const float* cur = x;
    for (int l = 0; l < N_LAYERS; l++) {
        aggregate_kernel<<<agg_blocks, 256>>>(cur, agg_buf, rowptr, esrc);
        mlp_kernel<<<mlp_blocks, 256>>>(
            agg_buf, h_buf,
            W1 + l * DIM * DIM, b1 + l * DIM,
            gamma + l * DIM, beta + l * DIM,
            rmean + l * DIM, rvar + l * DIM,
            W2 + l * DIM * DIM, b2 + l * DIM);
        cur = h_buf;
    }

    // --- pool + head ---
    zero_pool_kernel<<<(N_GRAPHS * DIM + 255) / 256, 256>>>(pool_buf);
    pool_kernel<<<(N_NODES + 1023) / 1024, 64>>>(h_buf, batch, pool_buf);
    head_kernel<<<1, 128>>>(pool_buf, lin1_w, lin1_b, lin2_w, lin2_b, out);
}

// round 6
// speedup vs baseline: 2.4278x; 1.2171x over previous
#include <cuda_runtime.h>
#include <cuda_bf16.h>
#include <cstdint>

#define N_NODES 100000
#define N_EDGES 1600000
#define DIM 64
#define N_GRAPHS 128
#define N_LAYERS 5
#define BN_EPS 1e-5f

#define SCAN_B 1024
#define N_SCAN_BLK ((N_NODES + SCAN_B - 1) / SCAN_B)   // 98

// Scratch (allocation-free rule: __device__ globals)
// Ping-pong buffers: fused layer kernel reads one, writes the other.
__device__ float g_h0[N_NODES * DIM];
__device__ float g_h1[N_NODES * DIM];
__device__ float g_pool[N_GRAPHS * DIM];
__device__ int   g_deg[N_NODES];
__device__ int   g_rowptr[N_NODES + 1];
__device__ int   g_cursor[N_NODES];
__device__ int   g_esrc[N_EDGES];
__device__ int   g_partials[128];   // >= N_SCAN_BLK

// ---------------------------------------------------------------------------
// CSR build (once per launch; edge_index is layer-invariant)
// ---------------------------------------------------------------------------
__global__ void zero_deg_kernel(int* __restrict__ deg) {
    int i = blockIdx.x * blockDim.x + threadIdx.x;
    if (i < N_NODES) deg[i] = 0;
}

__global__ void hist_kernel(const int* __restrict__ ei, int* __restrict__ deg) {
    int e = blockIdx.x * blockDim.x + threadIdx.x;
    if (e < N_EDGES) atomicAdd(&deg[ei[N_EDGES + e]], 1);
}

__global__ void scan1_kernel(const int* __restrict__ deg, int* __restrict__ excl,
                             int* __restrict__ partials) {
    __shared__ int sh[SCAN_B];
    int t = threadIdx.x;
    int idx = blockIdx.x * SCAN_B + t;
    int v = (idx < N_NODES) ? deg[idx] : 0;
    sh[t] = v;
    __syncthreads();
#pragma unroll
    for (int off = 1; off < SCAN_B; off <<= 1) {
        int add = (t >= off) ? sh[t - off] : 0;
        __syncthreads();
        sh[t] += add;
        __syncthreads();
    }
    if (idx < N_NODES) excl[idx] = sh[t] - v;
    if (t == SCAN_B - 1) partials[blockIdx.x] = sh[t];
}

__global__ void scan2_kernel(int* __restrict__ partials) {
    __shared__ int sh[128];
    int t = threadIdx.x;
    int v = (t < N_SCAN_BLK) ? partials[t] : 0;
    sh[t] = v;
    __syncthreads();
#pragma unroll
    for (int off = 1; off < 128; off <<= 1) {
        int add = (t >= off) ? sh[t - off] : 0;
        __syncthreads();
        sh[t] += add;
        __syncthreads();
    }
    if (t < N_SCAN_BLK) partials[t] = sh[t] - v;
}

__global__ void scan3_kernel(int* __restrict__ rowptr, int* __restrict__ cursor,
                             const int* __restrict__ partials) {
    int idx = blockIdx.x * blockDim.x + threadIdx.x;
    if (idx < N_NODES) {
        int val = rowptr[idx] + partials[idx >> 10];
        rowptr[idx] = val;
        cursor[idx] = val;
        if (idx == 0) rowptr[N_NODES] = N_EDGES;
    }
}

__global__ void fill_kernel(const int* __restrict__ ei, int* __restrict__ cursor,
                            int* __restrict__ esrc) {
    int e = blockIdx.x * blockDim.x + threadIdx.x;
    if (e < N_EDGES) {
        int d = ei[N_EDGES + e];
        int pos = atomicAdd(&cursor[d], 1);
        esrc[pos] = ei[e];
    }
}

// ---------------------------------------------------------------------------
// Fused layer: sX = gather(h) ; out = relu( relu(BN(sX@W1+b1)) @ W2 + b2 )
// h and out MUST NOT alias (caller ping-pongs buffers).
// Block: 256 threads, 64 nodes.
// Gather: 16 threads/node (float4/thread), 16 nodes concurrent, 4 batches.
// GEMM: R3-proven C++ float4-weight FFMA. Thread (nd,ng): 4 nodes x 4 dims.
// ---------------------------------------------------------------------------
__global__ void __launch_bounds__(256) layer_kernel(
    const float* __restrict__ h, float* __restrict__ out,
    const int* __restrict__ rowptr, const int* __restrict__ esrc,
    const float* __restrict__ W1, const float* __restrict__ b1,
    const float* __restrict__ gamma, const float* __restrict__ beta,
    const float* __restrict__ rmean, const float* __restrict__ rvar,
    const float* __restrict__ W2, const float* __restrict__ b2) {
    __shared__ float sW[DIM][DIM];       // 16 KB
    __shared__ float sX[DIM][DIM + 4];   // float4-aligned row padding
    __shared__ float sA[DIM], sB[DIM];

    int tid = threadIdx.x;
    int node0 = blockIdx.x * 64;

    // load W1 + BN fold (independent of gather)
    for (int i = tid; i < DIM * DIM; i += 256) sW[i >> 6][i & 63] = W1[i];
    if (tid < DIM) {
        float s = gamma[tid] * rsqrtf(rvar[tid] + BN_EPS);
        sA[tid] = s;
        sB[tid] = (b1[tid] - rmean[tid]) * s + beta[tid];
    }

    // ---- gather phase: agg -> sX ----
    int g16 = tid >> 4;        // node slot 0..15
    int l16 = tid & 15;        // dim quad  0..15
#pragma unroll
    for (int nb = 0; nb < 4; nb++) {
        int row = nb * 16 + g16;
        int node = node0 + row;
        float4 acc = make_float4(0.f, 0.f, 0.f, 0.f);
        if (node < N_NODES) {
            acc = *reinterpret_cast<const float4*>(&h[node * DIM + l16 * 4]);
            int beg = rowptr[node];
            int end = rowptr[node + 1];
            int j = beg;
            for (; j + 1 < end; j += 2) {
                int s0 = esrc[j], s1 = esrc[j + 1];
                float4 v0 = *reinterpret_cast<const float4*>(&h[s0 * DIM + l16 * 4]);
                float4 v1 = *reinterpret_cast<const float4*>(&h[s1 * DIM + l16 * 4]);
                acc.x += v0.x + v1.x;
                acc.y += v0.y + v1.y;
                acc.z += v0.z + v1.z;
                acc.w += v0.w + v1.w;
            }
            if (j < end) {
                float4 v = *reinterpret_cast<const float4*>(&h[esrc[j] * DIM + l16 * 4]);
                acc.x += v.x; acc.y += v.y; acc.z += v.z; acc.w += v.w;
            }
        }
        *reinterpret_cast<float4*>(&sX[row][l16 * 4]) = acc;
    }
    __syncthreads();

    int nd = tid & 15;   // dim group: dims [nd*4, nd*4+4)
    int ng = tid >> 4;   // node base: nodes {ng, ng+16, ng+32, ng+48}

    // ---- GEMM 1 ----
    float acc[4][4];
#pragma unroll
    for (int i = 0; i < 4; i++)
#pragma unroll
        for (int j = 0; j < 4; j++) acc[i][j] = 0.f;

#pragma unroll 8
    for (int k = 0; k < DIM; k++) {
        float4 w = *reinterpret_cast<const float4*>(&sW[k][nd * 4]);
        float x0 = sX[ng][k];
        float x1 = sX[ng + 16][k];
        float x2 = sX[ng + 32][k];
        float x3 = sX[ng + 48][k];
        acc[0][0] += x0 * w.x; acc[0][1] += x0 * w.y; acc[0][2] += x0 * w.z; acc[0][3] += x0 * w.w;
        acc[1][0] += x1 * w.x; acc[1][1] += x1 * w.y; acc[1][2] += x1 * w.z; acc[1][3] += x1 * w.w;
        acc[2][0] += x2 * w.x; acc[2][1] += x2 * w.y; acc[2][2] += x2 * w.z; acc[2][3] += x2 * w.w;
        acc[3][0] += x3 * w.x; acc[3][1] += x3 * w.y; acc[3][2] += x3 * w.z; acc[3][3] += x3 * w.w;
    }
    __syncthreads();  // done reading sW/sX

    // BN + relu -> sX ; load W2
#pragma unroll
    for (int i = 0; i < 4; i++) {
#pragma unroll
        for (int j = 0; j < 4; j++) {
            int d = nd * 4 + j;
            sX[ng + 16 * i][d] = fmaxf(acc[i][j] * sA[d] + sB[d], 0.f);
        }
    }
    for (int i = tid; i < DIM * DIM; i += 256) sW[i >> 6][i & 63] = W2[i];
    __syncthreads();

    // ---- GEMM 2 ----
#pragma unroll
    for (int i = 0; i < 4; i++)
#pragma unroll
        for (int j = 0; j < 4; j++) acc[i][j] = 0.f;

#pragma unroll 8
    for (int k = 0; k < DIM; k++) {
        float4 w = *reinterpret_cast<const float4*>(&sW[k][nd * 4]);
        float x0 = sX[ng][k];
        float x1 = sX[ng + 16][k];
        float x2 = sX[ng + 32][k];
        float x3 = sX[ng + 48][k];
        acc[0][0] += x0 * w.x; acc[0][1] += x0 * w.y; acc[0][2] += x0 * w.z; acc[0][3] += x0 * w.w;
        acc[1][0] += x1 * w.x; acc[1][1] += x1 * w.y; acc[1][2] += x1 * w.z; acc[1][3] += x1 * w.w;
        acc[2][0] += x2 * w.x; acc[2][1] += x2 * w.y; acc[2][2] += x2 * w.z; acc[2][3] += x2 * w.w;
        acc[3][0] += x3 * w.x; acc[3][1] += x3 * w.y; acc[3][2] += x3 * w.z; acc[3][3] += x3 * w.w;
    }

    // + b2, relu, store
    float4 bb = *reinterpret_cast<const float4*>(&b2[nd * 4]);
#pragma unroll
    for (int i = 0; i < 4; i++) {
        int node = node0 + ng + 16 * i;
        if (node < N_NODES) {
            float4 o;
            o.x = fmaxf(acc[i][0] + bb.x, 0.f);
            o.y = fmaxf(acc[i][1] + bb.y, 0.f);
            o.z = fmaxf(acc[i][2] + bb.z, 0.f);
            o.w = fmaxf(acc[i][3] + bb.w, 0.f);
            *reinterpret_cast<float4*>(&out[node * DIM + nd * 4]) = o;
        }
    }
}

// ---------------------------------------------------------------------------
// Pool + head
// ---------------------------------------------------------------------------
__global__ void zero_pool_kernel(float* __restrict__ pool) {
    int i = blockIdx.x * blockDim.x + threadIdx.x;
    if (i < N_GRAPHS * DIM) pool[i] = 0.f;
}

__global__ void pool_kernel(const float* __restrict__ h,
                            const int* __restrict__ batch,
                            float* __restrict__ pool) {
    const int NPB = 1024;
    int d = threadIdx.x;
    int start = blockIdx.x * NPB;
    if (start >= N_NODES) return;
    int end = min(start + NPB, N_NODES);
    int g = batch[start];
    float acc = 0.f;
    for (int node = start; node < end; node++) {
        int bg = batch[node];
        if (bg != g) {
            atomicAdd(&pool[g * DIM + d], acc);
            acc = 0.f;
            g = bg;
        }
        acc += h[node * DIM + d];
    }
    atomicAdd(&pool[g * DIM + d], acc);
}

__global__ void head_kernel(const float* __restrict__ pool,
                            const float* __restrict__ w1, const float* __restrict__ b1v,
                            const float* __restrict__ w2, const float* __restrict__ b2v,
                            float* __restrict__ out) {
    __shared__ float sW[DIM][DIM];
    __shared__ float sH[N_GRAPHS][DIM];
    int tid = threadIdx.x;
    for (int i = tid; i < DIM * DIM; i += 128) sW[i >> 6][i & 63] = w1[i];
    __syncthreads();

    int g = tid;
    float row[DIM];
#pragma unroll
    for (int k = 0; k < DIM; k++) row[k] = pool[g * DIM + k];
#pragma unroll 4
    for (int j = 0; j < DIM; j++) {
        float acc = b1v[j];
#pragma unroll
        for (int k = 0; k < DIM; k++) acc += row[k] * sW[k][j];
        sH[g][j] = fmaxf(acc, 0.f);
    }
    __syncthreads();
#pragma unroll
    for (int o = 0; o < 10; o++) {
        float acc = b2v[o];
#pragma unroll
        for (int k = 0; k < DIM; k++) acc += sH[g][k] * w2[k * 10 + o];
        out[g * 10 + o] = acc;
    }
}

// ---------------------------------------------------------------------------
extern "C" void kernel_launch(void* const* d_in, const int* in_sizes, int n_in,
                              void* d_out, int out_size) {
    const float* x      = (const float*)d_in[0];
    const int*   ei     = (const int*)d_in[1];
    const int*   batch  = (const int*)d_in[2];
    const float* W1     = (const float*)d_in[3];
    const float* b1     = (const float*)d_in[4];
    const float* gamma  = (const float*)d_in[5];
    const float* beta   = (const float*)d_in[6];
    const float* rmean  = (const float*)d_in[7];
    const float* rvar   = (const float*)d_in[8];
    const float* W2     = (const float*)d_in[9];
    const float* b2     = (const float*)d_in[10];
    const float* lin1_w = (const float*)d_in[11];
    const float* lin1_b = (const float*)d_in[12];
    const float* lin2_w = (const float*)d_in[13];
    const float* lin2_b = (const float*)d_in[14];
    float* out = (float*)d_out;

    float *h0, *h1, *pool_buf;
    int *deg, *rowptr, *cursor, *esrc, *partials;
    cudaGetSymbolAddress((void**)&h0, g_h0);
    cudaGetSymbolAddress((void**)&h1, g_h1);
    cudaGetSymbolAddress((void**)&pool_buf, g_pool);
    cudaGetSymbolAddress((void**)&deg, g_deg);
    cudaGetSymbolAddress((void**)&rowptr, g_rowptr);
    cudaGetSymbolAddress((void**)&cursor, g_cursor);
    cudaGetSymbolAddress((void**)&esrc, g_esrc);
    cudaGetSymbolAddress((void**)&partials, g_partials);

    const int eb = (N_EDGES + 255) / 256;
    const int nb = (N_NODES + 255) / 256;

    // --- CSR build (once; reused by all 5 layers) ---
    zero_deg_kernel<<<nb, 256>>>(deg);
    hist_kernel<<<eb, 256>>>(ei, deg);
    scan1_kernel<<<N_SCAN_BLK, SCAN_B>>>(deg, rowptr, partials);
    scan2_kernel<<<1, 128>>>(partials);
    scan3_kernel<<<nb, 256>>>(rowptr, cursor, partials);
    fill_kernel<<<eb, 256>>>(ei, cursor, esrc);

    // --- 5 fused GIN layers (ping-pong: never read+write same buffer) ---
    const int layer_blocks = (N_NODES + 63) / 64;
    const float* cur = x;
    float* dst = h0;
    for (int l = 0; l < N_LAYERS; l++) {
        layer_kernel<<<layer_blocks, 256>>>(
            cur, dst, rowptr, esrc,
            W1 + l * DIM * DIM, b1 + l * DIM,
            gamma + l * DIM, beta + l * DIM,
            rmean + l * DIM, rvar + l * DIM,
            W2 + l * DIM * DIM, b2 + l * DIM);
        cur = dst;
        dst = (dst == h0) ? h1 : h0;
    }
    const float* hfin = cur;

    // --- pool + head ---
    zero_pool_kernel<<<(N_GRAPHS * DIM + 255) / 256, 256>>>(pool_buf);
    pool_kernel<<<(N_NODES + 1023) / 1024, 64>>>(hfin, batch, pool_buf);
    head_kernel<<<1, 128>>>(pool_buf, lin1_w, lin1_b, lin2_w, lin2_b, out);
}